// round 14
// baseline (speedup 1.0000x reference)
#include <cuda_runtime.h>
#include <cuda_bf16.h>
#include <cuda_fp16.h>
#include <math.h>
#include <cstdint>

// Problem dims (fixed for this bench)
#define BB 64
#define LL 2048
#define DD 1024
#define VV 50257
#define TOPK 5

#define NCHUNK 16
#define LPC (LL / NCHUNK)        // 128 rows per chunk

#define TNB 64                   // GEMM N tile (lexicon rows per block)
#define NBLK ((VV + TNB - 1) / TNB)   // 786
#define TKH 64                   // GEMM K tile (fp16 elements)
#define NIT (DD / TKH)           // 16
#define KPADH 72                 // padded k stride in halves (144B rows, conflict-free)
#define NCAND 128
#define BTOP 6
#define CSPAD 65                 // Cs row stride (floats)

// GEMM smem (bytes): A bufs x3 @0/9216/18432 (64x144B each);
// B bufs x2 @27648/36864 (64x144B each); s_xn @46080 (64f); s_yn @46336 (64f).
// Epilogue overlay: Cs 64x65 f @0 (16640B), tmp 128x6 u64 @16640 (6144B).
#define A_STG  9216
#define B_STG  9216
#define OFS_B  27648
#define OFS_XN 46080
#define OFS_YN 46336
#define GEMM_SMEM 46592
#define OFS_TMP 16640

typedef unsigned long long u64;

// Scratch (device globals; no allocations allowed)
__device__ float4 g_part[NCHUNK][BB][DD / 4];  // mean-pool partials (4 MB)
__device__ float  g_tse[BB][DD];               // exact fp32 pooled embeddings
__device__ __half g_ts16[BB][DD];              // fp16 pooled embeddings (mma A)
__device__ float  g_xnorm[BB];
__device__ float  g_ynorm[VV];
__device__ u64    g_btop[BB][NBLK][BTOP];      // per-(batch,block) top-6 keys (2.4 MB)

__device__ __forceinline__ uint32_t h2u(__half2 h) {
    return *reinterpret_cast<uint32_t*>(&h);
}

__device__ __forceinline__ void mma_f16(float c[4],
                                        uint32_t a0, uint32_t a1, uint32_t a2, uint32_t a3,
                                        uint32_t b0, uint32_t b1) {
    asm volatile(
        "mma.sync.aligned.m16n8k16.row.col.f32.f16.f16.f32 "
        "{%0,%1,%2,%3}, {%4,%5,%6,%7}, {%8,%9}, {%0,%1,%2,%3};"
        : "+f"(c[0]), "+f"(c[1]), "+f"(c[2]), "+f"(c[3])
        : "r"(a0), "r"(a1), "r"(a2), "r"(a3), "r"(b0), "r"(b1));
}

__device__ __forceinline__ void ldsm4(uint32_t& r0, uint32_t& r1, uint32_t& r2, uint32_t& r3,
                                      uint32_t addr) {
    asm volatile("ldmatrix.sync.aligned.m8n8.x4.shared.b16 {%0,%1,%2,%3}, [%4];"
                 : "=r"(r0), "=r"(r1), "=r"(r2), "=r"(r3) : "r"(addr));
}

// Orderable float <-> uint mapping
__device__ __forceinline__ unsigned int ford(float f) {
    unsigned int u = __float_as_uint(f);
    return (u & 0x80000000u) ? ~u : (u | 0x80000000u);
}
__device__ __forceinline__ float funord(unsigned int r) {
    unsigned int u = (r & 0x80000000u) ? (r & 0x7FFFFFFFu) : ~r;
    return __uint_as_float(u);
}
__device__ __forceinline__ u64 mkkey(float val, int v) {
    return ((u64)ford(val) << 32) | (unsigned)(VV - 1 - v);
}
__device__ __forceinline__ int key2idx(u64 k) {
    return VV - 1 - (int)(unsigned)(k & 0xFFFFFFFFu);
}
template <int K>
__device__ __forceinline__ void insK(u64 c[K], u64 x) {
    if (x <= c[K - 1]) return;
    c[K - 1] = x;
    #pragma unroll
    for (int i = K - 2; i >= 0; i--) {
        if (c[i + 1] > c[i]) {
            u64 t = c[i]; c[i] = c[i + 1]; c[i + 1] = t;
        }
    }
}

// ---------------------------------------------------------------------------
// Kernel 0: nop (launch-order shim so GEMM lands in ncu's profiled slot)
// ---------------------------------------------------------------------------
__global__ void nop_kernel() {}

// ---------------------------------------------------------------------------
// Kernel 1: mean-pool partial sums. grid=(NCHUNK, BB), block=256
// ---------------------------------------------------------------------------
__global__ void __launch_bounds__(256) mean_partial_kernel(const float* __restrict__ patch) {
    int t = threadIdx.x;
    int c = blockIdx.x;
    int b = blockIdx.y;
    const float4* p = reinterpret_cast<const float4*>(
                          patch + ((size_t)b * LL + (size_t)c * LPC) * DD) + t;
    float4 s = make_float4(0.f, 0.f, 0.f, 0.f);
    #pragma unroll 8
    for (int l = 0; l < LPC; l++) {
        float4 v = p[(size_t)l * (DD / 4)];
        s.x += v.x; s.y += v.y; s.z += v.z; s.w += v.w;
    }
    g_part[c][b][t] = s;
}

// ---------------------------------------------------------------------------
// Kernel 2: finalize mean, exact fp32 + fp16 ts, x norms. grid=BB, block=256
// ---------------------------------------------------------------------------
__global__ void __launch_bounds__(256) finalize_kernel() {
    int b = blockIdx.x;
    int t = threadIdx.x;
    float4 s = make_float4(0.f, 0.f, 0.f, 0.f);
    #pragma unroll
    for (int c = 0; c < NCHUNK; c++) {
        float4 v = g_part[c][b][t];
        s.x += v.x; s.y += v.y; s.z += v.z; s.w += v.w;
    }
    const float inv = 1.0f / (float)LL;
    s.x *= inv; s.y *= inv; s.z *= inv; s.w *= inv;
    reinterpret_cast<float4*>(g_tse[b])[t] = s;
    uint2 h;
    h.x = h2u(__float22half2_rn(make_float2(s.x, s.y)));
    h.y = h2u(__float22half2_rn(make_float2(s.z, s.w)));
    reinterpret_cast<uint2*>(g_ts16[b])[t] = h;

    float ss = s.x * s.x + s.y * s.y + s.z * s.z + s.w * s.w;
    #pragma unroll
    for (int o = 16; o; o >>= 1) ss += __shfl_xor_sync(0xFFFFFFFFu, ss, o);
    __shared__ float red[8];
    if ((t & 31) == 0) red[t >> 5] = ss;
    __syncthreads();
    if (t == 0) {
        float tot = 0.f;
        #pragma unroll
        for (int w = 0; w < 8; w++) tot += red[w];
        g_xnorm[b] = sqrtf(tot);
    }
}

// ---------------------------------------------------------------------------
// Kernel 3: fp16 mma GEMM, 128-thread CTAs, prefetch DISTANCE 2 on both
// operands: A = 3-stage cp.async (wait_group 1), B = 2 register sets (LDG for
// iter i+2 at iter i; STS for i+1 from the set loaded a full iteration ago).
// Fused y-norms + out_sim + per-(batch,block) top-6. grid=786, block=128.
// ---------------------------------------------------------------------------
__global__ void __launch_bounds__(128, 5) gemm_kernel(const float* __restrict__ lex,
                                                      float* __restrict__ out_sim) {
    extern __shared__ char smem8[];
    const uint32_t su = (uint32_t)__cvta_generic_to_shared(smem8);
    float* s_xn = reinterpret_cast<float*>(smem8 + OFS_XN);
    float* s_yn = reinterpret_cast<float*>(smem8 + OFS_YN);
    float* Cs   = reinterpret_cast<float*>(smem8);              // overlay
    u64*   tmp  = reinterpret_cast<u64*>(smem8 + OFS_TMP);      // overlay

    int tid = threadIdx.x;
    int v0 = blockIdx.x * TNB;
    int lane = tid & 31, wid = tid >> 5;   // 4 warps
    int g = lane >> 2, t4 = lane & 3;
    int m_base = (wid >> 1) * 32;          // ts rows: 0 or 32
    int n_base = (wid & 1) * 32;           // lex rows: 0 or 32

    if (tid < BB) s_xn[tid] = g_xnorm[tid];

    // ldmatrix per-lane byte offsets (row stride 144B; conflict-free)
    const int a_moff = (((lane >> 3) & 1) << 3) + (lane & 7);
    const int a_khi  = (lane >> 4) << 4;
    const uint32_t a_lane_off = (uint32_t)((m_base + a_moff) * 144 + a_khi);
    const int b_noff = ((lane >> 4) << 3) + (lane & 7);
    const int b_k8   = (((lane >> 3) & 1) << 4);
    const uint32_t b_lane_off = (uint32_t)(OFS_B + (n_base + b_noff) * 144 + b_k8);

    // B loader: 8 threads/row, rows brow+16i (4 passes), 2 float4 per row
    const int brow = tid >> 3;             // 0..15
    const int bq   = (tid & 7) * 4;

    float acc[2][4][4];
    #pragma unroll
    for (int mt = 0; mt < 2; mt++)
        #pragma unroll
        for (int nt = 0; nt < 4; nt++)
            #pragma unroll
            for (int r = 0; r < 4; r++) acc[mt][nt][r] = 0.f;
    float yacc[4] = {0.f, 0.f, 0.f, 0.f};
    uint2 b_pre[2][8];                     // two pipeline sets

    #define ISSUE_A(buf, k0) do {                                              \
        _Pragma("unroll")                                                      \
        for (int j = 0; j < 4; j++) {                                          \
            int idx = tid + 128 * j;                                           \
            int row = idx >> 3, c = idx & 7;                                   \
            uint32_t dst = su + (buf) * A_STG + (uint32_t)(row * 144 + c * 16);\
            const __half* src = &g_ts16[row][(k0) + c * 8];                    \
            asm volatile("cp.async.cg.shared.global [%0], [%1], 16;"           \
                         :: "r"(dst), "l"(src) : "memory");                    \
        }                                                                      \
        asm volatile("cp.async.commit_group;" ::: "memory");                   \
    } while (0)

    #define LOAD_B(k0, set) do {                                               \
        _Pragma("unroll")                                                      \
        for (int i = 0; i < 4; i++) {                                          \
            int v = v0 + brow + 16 * i;                                        \
            float4 w0 = make_float4(0.f, 0.f, 0.f, 0.f), w1 = w0;              \
            if (v < VV) {                                                      \
                const float* r = &lex[(size_t)v * DD + (k0)];                  \
                w0 = *reinterpret_cast<const float4*>(r + bq);                 \
                w1 = *reinterpret_cast<const float4*>(r + 32 + bq);            \
            }                                                                  \
            yacc[i] += w0.x*w0.x + w0.y*w0.y + w0.z*w0.z + w0.w*w0.w           \
                     + w1.x*w1.x + w1.y*w1.y + w1.z*w1.z + w1.w*w1.w;          \
            b_pre[set][2*i].x   = h2u(__float22half2_rn(make_float2(w0.x, w0.y))); \
            b_pre[set][2*i].y   = h2u(__float22half2_rn(make_float2(w0.z, w0.w))); \
            b_pre[set][2*i+1].x = h2u(__float22half2_rn(make_float2(w1.x, w1.y))); \
            b_pre[set][2*i+1].y = h2u(__float22half2_rn(make_float2(w1.z, w1.w))); \
        }                                                                      \
    } while (0)

    #define STS_B(buf, set) do {                                               \
        __half* Bb = reinterpret_cast<__half*>(smem8 + OFS_B + (buf) * B_STG); \
        _Pragma("unroll")                                                      \
        for (int i = 0; i < 4; i++) {                                          \
            *reinterpret_cast<uint2*>(&Bb[(brow + 16*i) * KPADH + bq])      = b_pre[set][2*i]; \
            *reinterpret_cast<uint2*>(&Bb[(brow + 16*i) * KPADH + 32 + bq]) = b_pre[set][2*i+1]; \
        }                                                                      \
    } while (0)

    // ---- prologue: A for iters 0,1 in flight; B iter0 in smem, iter1 in regs
    ISSUE_A(0, 0);
    ISSUE_A(1, TKH);
    LOAD_B(0, 0);
    STS_B(0, 0);
    LOAD_B(TKH, 1);
    asm volatile("cp.async.wait_group 1;" ::: "memory");   // A0 complete
    __syncthreads();

    for (int it = 0; it < NIT; it++) {
        // data for iter it+2: A -> stage (it+2)%3, B -> register set it&1
        if (it + 2 < NIT) {
            ISSUE_A((it + 2) % 3, (it + 2) * TKH);
            LOAD_B((it + 2) * TKH, it & 1);
        }
        // STS B for iter it+1 (loaded a full iteration ago)
        if (it + 1 < NIT) STS_B((it + 1) & 1, (it + 1) & 1);

        // ---- compute iter it: A stage it%3, B buf it&1 ----
        {
            const uint32_t Acur = su + (uint32_t)((it % 3) * A_STG);
            const uint32_t Bcur = su + (uint32_t)((it & 1) * B_STG);  // b_lane_off has OFS_B
            #pragma unroll
            for (int ks = 0; ks < 4; ks++) {
                uint32_t a[2][4], bf[4][2];
                #pragma unroll
                for (int mt = 0; mt < 2; mt++)
                    ldsm4(a[mt][0], a[mt][1], a[mt][2], a[mt][3],
                          Acur + a_lane_off + (uint32_t)(mt * 16 * 144 + ks * 32));
                #pragma unroll
                for (int p = 0; p < 2; p++)
                    ldsm4(bf[2 * p][0], bf[2 * p][1], bf[2 * p + 1][0], bf[2 * p + 1][1],
                          Bcur + b_lane_off + (uint32_t)(p * 16 * 144 + ks * 32));
                #pragma unroll
                for (int mt = 0; mt < 2; mt++)
                    #pragma unroll
                    for (int nt = 0; nt < 4; nt++)
                        mma_f16(acc[mt][nt], a[mt][0], a[mt][1], a[mt][2], a[mt][3],
                                bf[nt][0], bf[nt][1]);
            }
        }
        if (it + 1 < NIT) {
            if (it + 2 < NIT)
                asm volatile("cp.async.wait_group 1;" ::: "memory");
            else
                asm volatile("cp.async.wait_group 0;" ::: "memory");
            __syncthreads();
        }
    }

    // ---- y norms: reduce over the 8 threads sharing each row ----
    #pragma unroll
    for (int i = 0; i < 4; i++) {
        float ys = yacc[i];
        ys += __shfl_down_sync(0xFFFFFFFFu, ys, 4, 8);
        ys += __shfl_down_sync(0xFFFFFFFFu, ys, 2, 8);
        ys += __shfl_down_sync(0xFFFFFFFFu, ys, 1, 8);
        if ((tid & 7) == 0) {
            int n = brow + 16 * i;
            float yn = sqrtf(ys);
            s_yn[n] = yn;
            if (v0 + n < VV) g_ynorm[v0 + n] = yn;
        }
    }
    __syncthreads();  // tiles free; s_yn ready; overlay begins

    // ---- stage normalized tile in smem ----
    #pragma unroll
    for (int mt = 0; mt < 2; mt++) {
        int m0 = m_base + 16 * mt + g;
        float xn0 = s_xn[m0], xn1 = s_xn[m0 + 8];
        #pragma unroll
        for (int nt = 0; nt < 4; nt++) {
            int ncol = n_base + 8 * nt + 2 * t4;
            #pragma unroll
            for (int j = 0; j < 2; j++) {
                int v = v0 + ncol + j;
                float yn = s_yn[ncol + j];
                float s0 = acc[mt][nt][j]     / fmaxf(xn0 * yn, 1e-8f);
                float s1 = acc[mt][nt][2 + j] / fmaxf(xn1 * yn, 1e-8f);
                if (v >= VV) { s0 = -3.4e38f; s1 = -3.4e38f; }
                Cs[m0 * CSPAD + ncol + j]       = s0;
                Cs[(m0 + 8) * CSPAD + ncol + j] = s1;
            }
        }
    }
    __syncthreads();

    // ---- coalesced out_sim write (64 rows x 64 cols) ----
    #pragma unroll
    for (int i = 0; i < 32; i++) {
        int idx = tid + i * 128;
        int m = idx >> 6, col = idx & 63;
        int v = v0 + col;
        if (v < VV)
            out_sim[(size_t)m * VV + v] = Cs[m * CSPAD + col];
    }

    // ---- per-row top-6: 2 threads/row, 32 cols each ----
    {
        int row = tid >> 1, q = tid & 1;
        u64 t6[BTOP] = {0, 0, 0, 0, 0, 0};
        #pragma unroll
        for (int i = 0; i < 32; i++) {
            int col = q * 32 + i;
            int v = v0 + col;
            if (v < VV) insK<BTOP>(t6, mkkey(Cs[row * CSPAD + col], v));
        }
        #pragma unroll
        for (int i = 0; i < BTOP; i++) tmp[tid * BTOP + i] = t6[i];
    }
    __syncthreads();
    if (tid < BB) {
        u64 t6[BTOP] = {0, 0, 0, 0, 0, 0};
        #pragma unroll
        for (int q = 0; q < 2; q++)
            #pragma unroll
            for (int i = 0; i < BTOP; i++)
                insK<BTOP>(t6, tmp[(tid * 2 + q) * BTOP + i]);
        #pragma unroll
        for (int i = 0; i < BTOP; i++) g_btop[tid][blockIdx.x][i] = t6[i];
    }
}

// ---------------------------------------------------------------------------
// Kernel 4: merge. Phase A: top-5 over per-block maxes (valid conservative
// threshold). Phase B: skip-scan. Then exact fp32 recompute -> exact select
// -> gather. grid=BB, block=512.
// ---------------------------------------------------------------------------
__global__ void __launch_bounds__(512) merge_kernel(const float* __restrict__ lex,
                                                    float* __restrict__ out_topk) {
    int b = blockIdx.x;
    int t = threadIdx.x;
    int lane = t & 31, wid = t >> 5;

    __shared__ u64   wtop[16][5];
    __shared__ float s_thresh;
    __shared__ int   cand[NCAND];
    __shared__ float cval[NCAND];
    __shared__ int   ncand;
    __shared__ int   selci[TOPK];
    __shared__ int   selfin[TOPK];

    const u64* keys = &g_btop[b][0][0];

    // Phase A: top-5 over block maxes (keys[blk*BTOP], sorted desc per block)
    u64 t5[5] = {0, 0, 0, 0, 0};
    {
        u64 k0 = (t < NBLK) ? keys[(size_t)t * BTOP] : 0ull;
        u64 k1 = (t + 512 < NBLK) ? keys[(size_t)(t + 512) * BTOP] : 0ull;
        insK<5>(t5, k0);
        insK<5>(t5, k1);
    }
    #pragma unroll
    for (int o = 16; o; o >>= 1) {
        u64 ot[5];
        #pragma unroll
        for (int i = 0; i < 5; i++) ot[i] = __shfl_xor_sync(0xFFFFFFFFu, t5[i], o);
        #pragma unroll
        for (int i = 0; i < 5; i++) insK<5>(t5, ot[i]);
    }
    if (lane == 0) {
        #pragma unroll
        for (int i = 0; i < 5; i++) wtop[wid][i] = t5[i];
    }
    __syncthreads();
    if (wid == 0) {
        const u64* flat = &wtop[0][0];  // 80 keys
        u64 m5[5] = {0, 0, 0, 0, 0};
        insK<5>(m5, flat[lane]);
        insK<5>(m5, flat[lane + 32]);
        if (lane < 16) insK<5>(m5, flat[lane + 64]);
        #pragma unroll
        for (int o = 16; o; o >>= 1) {
            u64 ot[5];
            #pragma unroll
            for (int i = 0; i < 5; i++) ot[i] = __shfl_xor_sync(0xFFFFFFFFu, m5[i], o);
            #pragma unroll
            for (int i = 0; i < 5; i++) insK<5>(m5, ot[i]);
        }
        if (lane == 0) {
            s_thresh = funord((unsigned)(m5[4] >> 32)) - 5e-4f;
            ncand = 0;
        }
    }
    __syncthreads();

    // Phase B: skip-scan. Only blocks whose max >= t contribute.
    float thr = s_thresh;
    for (int blk = t; blk < NBLK; blk += 512) {
        u64 k0 = keys[(size_t)blk * BTOP];
        if (funord((unsigned)(k0 >> 32)) >= thr) {
            #pragma unroll
            for (int j = 0; j < BTOP; j++) {
                u64 k = keys[(size_t)blk * BTOP + j];
                if (funord((unsigned)(k >> 32)) >= thr) {
                    int slot = atomicAdd(&ncand, 1);
                    if (slot < NCAND) cand[slot] = key2idx(k);
                }
            }
        }
    }
    __syncthreads();
    int nc = min(ncand, NCAND);

    // Phase C: exact fp32 recompute (one warp per candidate, 16 warps)
    {
        const float4* ts4 = reinterpret_cast<const float4*>(g_tse[b]);
        for (int ci = wid; ci < nc; ci += 16) {
            int v = cand[ci];
            const float4* lx4 = reinterpret_cast<const float4*>(lex + (size_t)v * DD);
            float d = 0.f;
            #pragma unroll
            for (int j = 0; j < 8; j++) {
                float4 a = ts4[j * 32 + lane];
                float4 c = lx4[j * 32 + lane];
                d += a.x * c.x + a.y * c.y + a.z * c.z + a.w * c.w;
            }
            #pragma unroll
            for (int o = 16; o; o >>= 1) d += __shfl_xor_sync(0xFFFFFFFFu, d, o);
            if (lane == 0)
                cval[ci] = d / fmaxf(g_xnorm[b] * g_ynorm[v], 1e-8f);
        }
    }
    __syncthreads();

    // Phase D: exact top-5 over candidates (warp 0), tie-break lowest index
    if (t < 32) {
        for (int j = 0; j < TOPK; j++) {
            float bv = -1e30f;
            int bvi = 0x7FFFFFFF;
            int bci = -1;
            for (int ci = t; ci < nc; ci += 32) {
                bool used = false;
                #pragma unroll
                for (int jj = 0; jj < TOPK; jj++)
                    if (jj < j && selci[jj] == ci) used = true;
                if (used) continue;
                float x = cval[ci];
                int v = cand[ci];
                if (x > bv || (x == bv && v < bvi)) { bv = x; bvi = v; bci = ci; }
            }
            #pragma unroll
            for (int o = 16; o; o >>= 1) {
                float ov  = __shfl_xor_sync(0xFFFFFFFFu, bv, o);
                int   ovi = __shfl_xor_sync(0xFFFFFFFFu, bvi, o);
                int   oci = __shfl_xor_sync(0xFFFFFFFFu, bci, o);
                if (ov > bv || (ov == bv && ovi < bvi)) { bv = ov; bvi = ovi; bci = oci; }
            }
            if (t == 0) { selci[j] = bci; selfin[j] = bvi; }
            __syncwarp();
        }
    }
    __syncthreads();

    // Phase E: gather top-k lexicon rows
    for (int j = 0; j < TOPK; j++) {
        const float4* src = reinterpret_cast<const float4*>(lex + (size_t)selfin[j] * DD);
        float4* dst = reinterpret_cast<float4*>(out_topk + ((size_t)b * TOPK + j) * DD);
        if (t < DD / 4) dst[t] = src[t];
    }
}

// ---------------------------------------------------------------------------
extern "C" void kernel_launch(void* const* d_in, const int* in_sizes, int n_in,
                              void* d_out, int out_size) {
    const float* patch = (const float*)d_in[0];
    const float* lex   = (const float*)d_in[1];
    float* out      = (float*)d_out;
    float* out_topk = out;                                  // [64][5][1024]
    float* out_sim  = out + (size_t)BB * TOPK * DD;         // [64][50257]

    cudaFuncSetAttribute(gemm_kernel, cudaFuncAttributeMaxDynamicSharedMemorySize,
                         GEMM_SMEM);

    mean_partial_kernel<<<dim3(NCHUNK, BB), 256>>>(patch);
    finalize_kernel<<<BB, 256>>>();
    nop_kernel<<<1, 32>>>();   // shim: keeps gemm in the profiled launch slot
    gemm_kernel<<<NBLK, 128, GEMM_SMEM>>>(lex, out_sim);
    merge_kernel<<<BB, 512>>>(lex, out_topk);
}

// round 15
// speedup vs baseline: 1.1424x; 1.1424x over previous
#include <cuda_runtime.h>
#include <cuda_bf16.h>
#include <cuda_fp16.h>
#include <math.h>
#include <cstdint>

// Problem dims (fixed for this bench)
#define BB 64
#define LL 2048
#define DD 1024
#define VV 50257
#define TOPK 5

#define NCHUNK 16
#define LPC (LL / NCHUNK)        // 128 rows per chunk

#define TNB 384                  // GEMM tile: lexicon rows per CTA (48 per warp)
#define NBLK ((VV + TNB - 1) / TNB)   // 131 (single wave on 148 SMs)
#define TKF 32                   // k elements per iteration
#define NIT (DD / TKF)           // 32
#define NCAND 128
#define BTOP 6
#define CSPAD 392                // Cs row stride (floats)

// GEMM smem (bytes):
//   A: 64 rows x 2064B (1024 halves + 8 pad)          @0      (132096)
//   B: 2 bufs x 384 rows x 80B (32 halves + 8 pad)    @132096 (2x30720)
//   s_xn (64 f)  @193536;  s_yn (384 f) @193792
// Epilogue overlay on [0..112640): Cs 64x392 f (100352) + tmp 256x6 u64
#define A_ROWB  2064
#define OFS_B0  132096
#define B_STG   30720
#define OFS_XN  193536
#define OFS_YN  193792
#define GEMM_SMEM 195328
#define OFS_TMP 100352

typedef unsigned long long u64;

// Scratch (device globals; no allocations allowed)
__device__ float4 g_part[NCHUNK][BB][DD / 4];  // mean-pool partials (4 MB)
__device__ float  g_tse[BB][DD];               // exact fp32 pooled embeddings
__device__ __half g_ts16[BB][DD];              // fp16 pooled embeddings (mma A)
__device__ float  g_xnorm[BB];
__device__ float  g_ynorm[VV];
__device__ u64    g_btop[BB][NBLK][BTOP];      // per-(batch,block) top-6 keys

__device__ __forceinline__ uint32_t h2u(__half2 h) {
    return *reinterpret_cast<uint32_t*>(&h);
}

__device__ __forceinline__ void mma_f16(float c[4],
                                        uint32_t a0, uint32_t a1, uint32_t a2, uint32_t a3,
                                        uint32_t b0, uint32_t b1) {
    asm volatile(
        "mma.sync.aligned.m16n8k16.row.col.f32.f16.f16.f32 "
        "{%0,%1,%2,%3}, {%4,%5,%6,%7}, {%8,%9}, {%0,%1,%2,%3};"
        : "+f"(c[0]), "+f"(c[1]), "+f"(c[2]), "+f"(c[3])
        : "r"(a0), "r"(a1), "r"(a2), "r"(a3), "r"(b0), "r"(b1));
}

__device__ __forceinline__ void ldsm4(uint32_t& r0, uint32_t& r1, uint32_t& r2, uint32_t& r3,
                                      uint32_t addr) {
    asm volatile("ldmatrix.sync.aligned.m8n8.x4.shared.b16 {%0,%1,%2,%3}, [%4];"
                 : "=r"(r0), "=r"(r1), "=r"(r2), "=r"(r3) : "r"(addr));
}

// Orderable float <-> uint mapping
__device__ __forceinline__ unsigned int ford(float f) {
    unsigned int u = __float_as_uint(f);
    return (u & 0x80000000u) ? ~u : (u | 0x80000000u);
}
__device__ __forceinline__ float funord(unsigned int r) {
    unsigned int u = (r & 0x80000000u) ? (r & 0x7FFFFFFFu) : ~r;
    return __uint_as_float(u);
}
__device__ __forceinline__ u64 mkkey(float val, int v) {
    return ((u64)ford(val) << 32) | (unsigned)(VV - 1 - v);
}
__device__ __forceinline__ int key2idx(u64 k) {
    return VV - 1 - (int)(unsigned)(k & 0xFFFFFFFFu);
}
template <int K>
__device__ __forceinline__ void insK(u64 c[K], u64 x) {
    if (x <= c[K - 1]) return;
    c[K - 1] = x;
    #pragma unroll
    for (int i = K - 2; i >= 0; i--) {
        if (c[i + 1] > c[i]) {
            u64 t = c[i]; c[i] = c[i + 1]; c[i + 1] = t;
        }
    }
}

// ---------------------------------------------------------------------------
// Kernel 0: nop (launch-order shim so GEMM lands in ncu's profiled slot)
// ---------------------------------------------------------------------------
__global__ void nop_kernel() {}

// ---------------------------------------------------------------------------
// Kernel 1: mean-pool partial sums. grid=(NCHUNK, BB), block=256
// ---------------------------------------------------------------------------
__global__ void __launch_bounds__(256) mean_partial_kernel(const float* __restrict__ patch) {
    int t = threadIdx.x;
    int c = blockIdx.x;
    int b = blockIdx.y;
    const float4* p = reinterpret_cast<const float4*>(
                          patch + ((size_t)b * LL + (size_t)c * LPC) * DD) + t;
    float4 s = make_float4(0.f, 0.f, 0.f, 0.f);
    #pragma unroll 8
    for (int l = 0; l < LPC; l++) {
        float4 v = p[(size_t)l * (DD / 4)];
        s.x += v.x; s.y += v.y; s.z += v.z; s.w += v.w;
    }
    g_part[c][b][t] = s;
}

// ---------------------------------------------------------------------------
// Kernel 2: finalize mean, exact fp32 + fp16 ts, x norms. grid=BB, block=256
// ---------------------------------------------------------------------------
__global__ void __launch_bounds__(256) finalize_kernel() {
    int b = blockIdx.x;
    int t = threadIdx.x;
    float4 s = make_float4(0.f, 0.f, 0.f, 0.f);
    #pragma unroll
    for (int c = 0; c < NCHUNK; c++) {
        float4 v = g_part[c][b][t];
        s.x += v.x; s.y += v.y; s.z += v.z; s.w += v.w;
    }
    const float inv = 1.0f / (float)LL;
    s.x *= inv; s.y *= inv; s.z *= inv; s.w *= inv;
    reinterpret_cast<float4*>(g_tse[b])[t] = s;
    uint2 h;
    h.x = h2u(__float22half2_rn(make_float2(s.x, s.y)));
    h.y = h2u(__float22half2_rn(make_float2(s.z, s.w)));
    reinterpret_cast<uint2*>(g_ts16[b])[t] = h;

    float ss = s.x * s.x + s.y * s.y + s.z * s.z + s.w * s.w;
    #pragma unroll
    for (int o = 16; o; o >>= 1) ss += __shfl_xor_sync(0xFFFFFFFFu, ss, o);
    __shared__ float red[8];
    if ((t & 31) == 0) red[t >> 5] = ss;
    __syncthreads();
    if (t == 0) {
        float tot = 0.f;
        #pragma unroll
        for (int w = 0; w < 8; w++) tot += red[w];
        g_xnorm[b] = sqrtf(tot);
    }
}

// ---------------------------------------------------------------------------
// Kernel 3: warp-autonomous fp16 GEMM. A (ts 64x1024 fp16) resident in smem
// (loaded once). Each of 8 warps privately streams its own 48 lexicon rows
// with a barrier-FREE double-buffered pipeline: raw LDG -> compute (hides
// latency) -> cvt+STS+syncwarp. Fused y-norms + out_sim + per-(batch,block)
// top-6. grid=131, block=256, 1 CTA/SM.
// ---------------------------------------------------------------------------
__global__ void __launch_bounds__(256, 1) gemm_kernel(const float* __restrict__ lex,
                                                      float* __restrict__ out_sim) {
    extern __shared__ char smem8[];
    const uint32_t su = (uint32_t)__cvta_generic_to_shared(smem8);
    float* s_xn = reinterpret_cast<float*>(smem8 + OFS_XN);
    float* s_yn = reinterpret_cast<float*>(smem8 + OFS_YN);
    float* Cs   = reinterpret_cast<float*>(smem8);              // overlay
    u64*   tmp  = reinterpret_cast<u64*>(smem8 + OFS_TMP);      // overlay

    int tid = threadIdx.x;
    int v0 = blockIdx.x * TNB;
    int lane = tid & 31, wid = tid >> 5;
    int g = lane >> 2, t4 = lane & 3;
    const int wn0 = wid * 48;              // warp's first lex row within tile

    if (tid < BB) s_xn[tid] = g_xnorm[tid];

    // ---- A prologue: 64 x 1024 halves via cp.async (once) ----
    #pragma unroll
    for (int j = 0; j < 32; j++) {
        int idx = tid + 256 * j;
        int row = idx >> 7, c = idx & 127;
        uint32_t dst = su + (uint32_t)(row * A_ROWB + c * 16);
        const __half* src = &g_ts16[row][c * 8];
        asm volatile("cp.async.cg.shared.global [%0], [%1], 16;"
                     :: "r"(dst), "l"(src) : "memory");
    }
    asm volatile("cp.async.commit_group;" ::: "memory");

    // ldsm lane offsets
    const int a_moff = (((lane >> 3) & 1) << 3) + (lane & 7);
    const int a_khi  = (lane >> 4) << 4;
    const int b_noff = ((lane >> 4) << 3) + (lane & 7);
    const int b_k8   = (((lane >> 3) & 1) << 4);

    // B loader: lane covers rows (lane>>3)+4j (j=0..11), float4 col = lane&7
    const int lr0 = lane >> 3;
    const int lc4 = (lane & 7) * 4;

    float acc[4][6][4];
    #pragma unroll
    for (int mt = 0; mt < 4; mt++)
        #pragma unroll
        for (int nt = 0; nt < 6; nt++)
            #pragma unroll
            for (int r = 0; r < 4; r++) acc[mt][nt][r] = 0.f;
    float yacc[12];
    #pragma unroll
    for (int j = 0; j < 12; j++) yacc[j] = 0.f;

    float4 raw[12];

    #define LDG_B_RAW(k0) do {                                                 \
        _Pragma("unroll")                                                      \
        for (int j = 0; j < 12; j++) {                                         \
            int v = v0 + wn0 + lr0 + 4 * j;                                    \
            raw[j] = (v < VV)                                                  \
                ? *reinterpret_cast<const float4*>(&lex[(size_t)v * DD + (k0) + lc4]) \
                : make_float4(0.f, 0.f, 0.f, 0.f);                             \
        }                                                                      \
    } while (0)

    #define CVT_STS_B(buf) do {                                                \
        __half* Bb = reinterpret_cast<__half*>(smem8 + OFS_B0 + (buf) * B_STG);\
        _Pragma("unroll")                                                      \
        for (int j = 0; j < 12; j++) {                                         \
            float4 w = raw[j];                                                 \
            yacc[j] += w.x * w.x + w.y * w.y + w.z * w.z + w.w * w.w;          \
            uint2 pk;                                                          \
            pk.x = h2u(__float22half2_rn(make_float2(w.x, w.y)));              \
            pk.y = h2u(__float22half2_rn(make_float2(w.z, w.w)));              \
            *reinterpret_cast<uint2*>(&Bb[(wn0 + lr0 + 4 * j) * 40 + lc4]) = pk; \
        }                                                                      \
        __syncwarp();                                                          \
    } while (0)

    // B iter 0 loads overlap the A cp.async wait
    LDG_B_RAW(0);
    asm volatile("cp.async.wait_group 0;" ::: "memory");
    __syncthreads();   // A resident + s_xn visible (only barrier before epilogue)
    CVT_STS_B(0);

    for (int it = 0; it < NIT; it++) {
        if (it + 1 < NIT) LDG_B_RAW((it + 1) * TKF);
        // ---- compute iter it (LDG latency hides under this) ----
        {
            const uint32_t Bcur = su + (uint32_t)(OFS_B0 + (it & 1) * B_STG);
            #pragma unroll
            for (int ks = 0; ks < 2; ks++) {
                int kb = it * 64 + ks * 32;   // byte offset within A row
                uint32_t a[4][4], bf[6][2];
                #pragma unroll
                for (int mt = 0; mt < 4; mt++)
                    ldsm4(a[mt][0], a[mt][1], a[mt][2], a[mt][3],
                          su + (uint32_t)((16 * mt + a_moff) * A_ROWB + kb + a_khi));
                #pragma unroll
                for (int p = 0; p < 3; p++)
                    ldsm4(bf[2 * p][0], bf[2 * p][1], bf[2 * p + 1][0], bf[2 * p + 1][1],
                          Bcur + (uint32_t)((wn0 + 16 * p + b_noff) * 80 + ks * 32 + b_k8));
                #pragma unroll
                for (int mt = 0; mt < 4; mt++)
                    #pragma unroll
                    for (int nt = 0; nt < 6; nt++)
                        mma_f16(acc[mt][nt], a[mt][0], a[mt][1], a[mt][2], a[mt][3],
                                bf[nt][0], bf[nt][1]);
            }
        }
        if (it + 1 < NIT) CVT_STS_B((it + 1) & 1);
    }

    // ---- y norms: reduce 8 lanes (same lane>>3 group) per row ----
    #pragma unroll
    for (int j = 0; j < 12; j++) {
        float ys = yacc[j];
        ys += __shfl_down_sync(0xFFFFFFFFu, ys, 4, 8);
        ys += __shfl_down_sync(0xFFFFFFFFu, ys, 2, 8);
        ys += __shfl_down_sync(0xFFFFFFFFu, ys, 1, 8);
        if ((lane & 7) == 0) {
            int r = lr0 + 4 * j;              // 0..47
            float yn = sqrtf(ys);
            s_yn[wn0 + r] = yn;
            if (v0 + wn0 + r < VV) g_ynorm[v0 + wn0 + r] = yn;
        }
    }
    __syncthreads();   // all warps done with A/B tiles; s_yn complete; overlay

    // ---- stage normalized tile into Cs (overlays A/B region) ----
    #pragma unroll
    for (int mt = 0; mt < 4; mt++) {
        int m0 = 16 * mt + g;
        float xn0 = s_xn[m0], xn1 = s_xn[m0 + 8];
        #pragma unroll
        for (int nt = 0; nt < 6; nt++) {
            int ncol = wn0 + 8 * nt + 2 * t4;
            #pragma unroll
            for (int j = 0; j < 2; j++) {
                int v = v0 + ncol + j;
                float yn = s_yn[ncol + j];
                float s0 = acc[mt][nt][j]     / fmaxf(xn0 * yn, 1e-8f);
                float s1 = acc[mt][nt][2 + j] / fmaxf(xn1 * yn, 1e-8f);
                if (v >= VV) { s0 = -3.4e38f; s1 = -3.4e38f; }
                Cs[m0 * CSPAD + ncol + j]       = s0;
                Cs[(m0 + 8) * CSPAD + ncol + j] = s1;
            }
        }
    }
    __syncthreads();

    // ---- coalesced out_sim write (64 rows x 384 cols) ----
    for (int m = 0; m < BB; m++) {
        for (int c = tid; c < TNB; c += 256) {
            int v = v0 + c;
            if (v < VV)
                out_sim[(size_t)m * VV + v] = Cs[m * CSPAD + c];
        }
    }

    // ---- per-row top-6: 4 threads/row, 96 cols each ----
    {
        int row = tid >> 2, q = tid & 3;
        u64 t6[BTOP] = {0, 0, 0, 0, 0, 0};
        for (int i = 0; i < 96; i++) {
            int col = q * 96 + i;
            int v = v0 + col;
            if (v < VV) insK<BTOP>(t6, mkkey(Cs[row * CSPAD + col], v));
        }
        #pragma unroll
        for (int i = 0; i < BTOP; i++) tmp[tid * BTOP + i] = t6[i];
    }
    __syncthreads();
    if (tid < BB) {
        u64 t6[BTOP] = {0, 0, 0, 0, 0, 0};
        #pragma unroll
        for (int q = 0; q < 4; q++)
            #pragma unroll
            for (int i = 0; i < BTOP; i++)
                insK<BTOP>(t6, tmp[(tid * 4 + q) * BTOP + i]);
        #pragma unroll
        for (int i = 0; i < BTOP; i++) g_btop[tid][blockIdx.x][i] = t6[i];
    }
}

// ---------------------------------------------------------------------------
// Kernel 4: merge. Phase A: top-5 over per-block maxes (conservative valid
// threshold). Phase B: skip-scan. Exact fp32 recompute -> exact select ->
// gather. grid=BB, block=512.
// ---------------------------------------------------------------------------
__global__ void __launch_bounds__(512) merge_kernel(const float* __restrict__ lex,
                                                    float* __restrict__ out_topk) {
    int b = blockIdx.x;
    int t = threadIdx.x;
    int lane = t & 31, wid = t >> 5;

    __shared__ u64   wtop[16][5];
    __shared__ float s_thresh;
    __shared__ int   cand[NCAND];
    __shared__ float cval[NCAND];
    __shared__ int   ncand;
    __shared__ int   selci[TOPK];
    __shared__ int   selfin[TOPK];

    const u64* keys = &g_btop[b][0][0];

    // Phase A: top-5 over block maxes (keys[blk*BTOP], sorted desc per block)
    u64 t5[5] = {0, 0, 0, 0, 0};
    if (t < NBLK) insK<5>(t5, keys[(size_t)t * BTOP]);
    #pragma unroll
    for (int o = 16; o; o >>= 1) {
        u64 ot[5];
        #pragma unroll
        for (int i = 0; i < 5; i++) ot[i] = __shfl_xor_sync(0xFFFFFFFFu, t5[i], o);
        #pragma unroll
        for (int i = 0; i < 5; i++) insK<5>(t5, ot[i]);
    }
    if (lane == 0) {
        #pragma unroll
        for (int i = 0; i < 5; i++) wtop[wid][i] = t5[i];
    }
    __syncthreads();
    if (wid == 0) {
        const u64* flat = &wtop[0][0];  // 80 keys
        u64 m5[5] = {0, 0, 0, 0, 0};
        insK<5>(m5, flat[lane]);
        insK<5>(m5, flat[lane + 32]);
        if (lane < 16) insK<5>(m5, flat[lane + 64]);
        #pragma unroll
        for (int o = 16; o; o >>= 1) {
            u64 ot[5];
            #pragma unroll
            for (int i = 0; i < 5; i++) ot[i] = __shfl_xor_sync(0xFFFFFFFFu, m5[i], o);
            #pragma unroll
            for (int i = 0; i < 5; i++) insK<5>(m5, ot[i]);
        }
        if (lane == 0) {
            s_thresh = funord((unsigned)(m5[4] >> 32)) - 5e-4f;
            ncand = 0;
        }
    }
    __syncthreads();

    // Phase B: skip-scan blocks whose max >= thresh
    float thr = s_thresh;
    for (int blk = t; blk < NBLK; blk += 512) {
        u64 k0 = keys[(size_t)blk * BTOP];
        if (funord((unsigned)(k0 >> 32)) >= thr) {
            #pragma unroll
            for (int j = 0; j < BTOP; j++) {
                u64 k = keys[(size_t)blk * BTOP + j];
                if (funord((unsigned)(k >> 32)) >= thr) {
                    int slot = atomicAdd(&ncand, 1);
                    if (slot < NCAND) cand[slot] = key2idx(k);
                }
            }
        }
    }
    __syncthreads();
    int nc = min(ncand, NCAND);

    // Phase C: exact fp32 recompute (one warp per candidate, 16 warps)
    {
        const float4* ts4 = reinterpret_cast<const float4*>(g_tse[b]);
        for (int ci = wid; ci < nc; ci += 16) {
            int v = cand[ci];
            const float4* lx4 = reinterpret_cast<const float4*>(lex + (size_t)v * DD);
            float d = 0.f;
            #pragma unroll
            for (int j = 0; j < 8; j++) {
                float4 a = ts4[j * 32 + lane];
                float4 c = lx4[j * 32 + lane];
                d += a.x * c.x + a.y * c.y + a.z * c.z + a.w * c.w;
            }
            #pragma unroll
            for (int o = 16; o; o >>= 1) d += __shfl_xor_sync(0xFFFFFFFFu, d, o);
            if (lane == 0)
                cval[ci] = d / fmaxf(g_xnorm[b] * g_ynorm[v], 1e-8f);
        }
    }
    __syncthreads();

    // Phase D: exact top-5 over candidates (warp 0), tie-break lowest index
    if (t < 32) {
        for (int j = 0; j < TOPK; j++) {
            float bv = -1e30f;
            int bvi = 0x7FFFFFFF;
            int bci = -1;
            for (int ci = t; ci < nc; ci += 32) {
                bool used = false;
                #pragma unroll
                for (int jj = 0; jj < TOPK; jj++)
                    if (jj < j && selci[jj] == ci) used = true;
                if (used) continue;
                float x = cval[ci];
                int v = cand[ci];
                if (x > bv || (x == bv && v < bvi)) { bv = x; bvi = v; bci = ci; }
            }
            #pragma unroll
            for (int o = 16; o; o >>= 1) {
                float ov  = __shfl_xor_sync(0xFFFFFFFFu, bv, o);
                int   ovi = __shfl_xor_sync(0xFFFFFFFFu, bvi, o);
                int   oci = __shfl_xor_sync(0xFFFFFFFFu, bci, o);
                if (ov > bv || (ov == bv && ovi < bvi)) { bv = ov; bvi = ovi; bci = oci; }
            }
            if (t == 0) { selci[j] = bci; selfin[j] = bvi; }
            __syncwarp();
        }
    }
    __syncthreads();

    // Phase E: gather top-k lexicon rows
    for (int j = 0; j < TOPK; j++) {
        const float4* src = reinterpret_cast<const float4*>(lex + (size_t)selfin[j] * DD);
        float4* dst = reinterpret_cast<float4*>(out_topk + ((size_t)b * TOPK + j) * DD);
        if (t < DD / 4) dst[t] = src[t];
    }
}

// ---------------------------------------------------------------------------
extern "C" void kernel_launch(void* const* d_in, const int* in_sizes, int n_in,
                              void* d_out, int out_size) {
    const float* patch = (const float*)d_in[0];
    const float* lex   = (const float*)d_in[1];
    float* out      = (float*)d_out;
    float* out_topk = out;                                  // [64][5][1024]
    float* out_sim  = out + (size_t)BB * TOPK * DD;         // [64][50257]

    cudaFuncSetAttribute(gemm_kernel, cudaFuncAttributeMaxDynamicSharedMemorySize,
                         GEMM_SMEM);

    mean_partial_kernel<<<dim3(NCHUNK, BB), 256>>>(patch);
    finalize_kernel<<<BB, 256>>>();
    nop_kernel<<<1, 32>>>();   // shim: keeps gemm in the profiled launch slot
    gemm_kernel<<<NBLK, 256, GEMM_SMEM>>>(lex, out_sim);
    merge_kernel<<<BB, 512>>>(lex, out_topk);
}

// round 16
// speedup vs baseline: 1.2524x; 1.0962x over previous
#include <cuda_runtime.h>
#include <cuda_bf16.h>
#include <cuda_fp16.h>
#include <math.h>
#include <cstdint>

// Problem dims (fixed for this bench)
#define BB 64
#define LL 2048
#define DD 1024
#define VV 50257
#define TOPK 5

#define NCHUNK 16
#define LPC (LL / NCHUNK)        // 128 rows per chunk

#define TNB 128                  // GEMM N tile
#define NBLK ((VV + TNB - 1) / TNB)   // 393
#define TKH 64                   // GEMM K tile (fp16 elements)
#define NIT (DD / TKH)           // 16
#define KPADH 72                 // padded k stride in halves (144B rows, conflict-free)
#define NCAND 128
#define BTOP 6
#define CSPAD 129                // Cs row stride (floats)

// Smem blob (bytes): A0 @0, A1 @9216 (64x144B); B0 @18432, B1 @36864
// (128x144B); s_xn @55296 (64f); s_yn @55552 (128f).
// Epilogue overlay: Cs 64x129 f @0 (33024B), tmp 256x6 u64 @33024 (12288B).
#define A_STG  9216
#define B_STG  18432
#define OFS_B  18432
#define OFS_XN 55296
#define OFS_YN 55552
#define GEMM_SMEM 56064
#define OFS_TMP 33024

typedef unsigned long long u64;

// Scratch (device globals; no allocations allowed)
__device__ float4 g_part[NCHUNK][BB][DD / 4];  // mean-pool partials (4 MB)
__device__ float  g_tse[BB][DD];               // exact fp32 pooled embeddings
__device__ __half g_ts16[BB][DD];              // fp16 pooled embeddings (mma A)
__device__ float  g_xnorm[BB];
__device__ float  g_ynorm[VV];
__device__ u64    g_btop[BB][NBLK][BTOP];      // per-(batch,block) top-6 keys (1.2 MB)

__device__ __forceinline__ uint32_t h2u(__half2 h) {
    return *reinterpret_cast<uint32_t*>(&h);
}

__device__ __forceinline__ void mma_f16(float c[4],
                                        uint32_t a0, uint32_t a1, uint32_t a2, uint32_t a3,
                                        uint32_t b0, uint32_t b1) {
    asm volatile(
        "mma.sync.aligned.m16n8k16.row.col.f32.f16.f16.f32 "
        "{%0,%1,%2,%3}, {%4,%5,%6,%7}, {%8,%9}, {%0,%1,%2,%3};"
        : "+f"(c[0]), "+f"(c[1]), "+f"(c[2]), "+f"(c[3])
        : "r"(a0), "r"(a1), "r"(a2), "r"(a3), "r"(b0), "r"(b1));
}

__device__ __forceinline__ void ldsm4(uint32_t& r0, uint32_t& r1, uint32_t& r2, uint32_t& r3,
                                      uint32_t addr) {
    asm volatile("ldmatrix.sync.aligned.m8n8.x4.shared.b16 {%0,%1,%2,%3}, [%4];"
                 : "=r"(r0), "=r"(r1), "=r"(r2), "=r"(r3) : "r"(addr));
}

// Streaming float4 load (evict-first: lexicon rows have zero reuse)
__device__ __forceinline__ float4 ldcs4(const float* p) {
    float4 v;
    asm volatile("ld.global.cs.v4.f32 {%0,%1,%2,%3}, [%4];"
                 : "=f"(v.x), "=f"(v.y), "=f"(v.z), "=f"(v.w) : "l"(p));
    return v;
}

// Orderable float <-> uint mapping
__device__ __forceinline__ unsigned int ford(float f) {
    unsigned int u = __float_as_uint(f);
    return (u & 0x80000000u) ? ~u : (u | 0x80000000u);
}
__device__ __forceinline__ float funord(unsigned int r) {
    unsigned int u = (r & 0x80000000u) ? (r & 0x7FFFFFFFu) : ~r;
    return __uint_as_float(u);
}
__device__ __forceinline__ u64 mkkey(float val, int v) {
    return ((u64)ford(val) << 32) | (unsigned)(VV - 1 - v);
}
__device__ __forceinline__ int key2idx(u64 k) {
    return VV - 1 - (int)(unsigned)(k & 0xFFFFFFFFu);
}
template <int K>
__device__ __forceinline__ void insK(u64 c[K], u64 x) {
    if (x <= c[K - 1]) return;
    c[K - 1] = x;
    #pragma unroll
    for (int i = K - 2; i >= 0; i--) {
        if (c[i + 1] > c[i]) {
            u64 t = c[i]; c[i] = c[i + 1]; c[i + 1] = t;
        }
    }
}

// ---------------------------------------------------------------------------
// Kernel 0: nop (launch-order shim so GEMM lands in ncu's profiled slot)
// ---------------------------------------------------------------------------
__global__ void nop_kernel() {}

// ---------------------------------------------------------------------------
// Kernel 1: mean-pool partial sums. grid=(NCHUNK, BB), block=256
// ---------------------------------------------------------------------------
__global__ void __launch_bounds__(256) mean_partial_kernel(const float* __restrict__ patch) {
    int t = threadIdx.x;
    int c = blockIdx.x;
    int b = blockIdx.y;
    const float4* p = reinterpret_cast<const float4*>(
                          patch + ((size_t)b * LL + (size_t)c * LPC) * DD) + t;
    float4 s = make_float4(0.f, 0.f, 0.f, 0.f);
    #pragma unroll 8
    for (int l = 0; l < LPC; l++) {
        float4 v = p[(size_t)l * (DD / 4)];
        s.x += v.x; s.y += v.y; s.z += v.z; s.w += v.w;
    }
    g_part[c][b][t] = s;
}

// ---------------------------------------------------------------------------
// Kernel 2: finalize mean, exact fp32 + fp16 ts, x norms. grid=BB, block=256
// ---------------------------------------------------------------------------
__global__ void __launch_bounds__(256) finalize_kernel() {
    int b = blockIdx.x;
    int t = threadIdx.x;
    float4 s = make_float4(0.f, 0.f, 0.f, 0.f);
    #pragma unroll
    for (int c = 0; c < NCHUNK; c++) {
        float4 v = g_part[c][b][t];
        s.x += v.x; s.y += v.y; s.z += v.z; s.w += v.w;
    }
    const float inv = 1.0f / (float)LL;
    s.x *= inv; s.y *= inv; s.z *= inv; s.w *= inv;
    reinterpret_cast<float4*>(g_tse[b])[t] = s;
    uint2 h;
    h.x = h2u(__float22half2_rn(make_float2(s.x, s.y)));
    h.y = h2u(__float22half2_rn(make_float2(s.z, s.w)));
    reinterpret_cast<uint2*>(g_ts16[b])[t] = h;

    float ss = s.x * s.x + s.y * s.y + s.z * s.z + s.w * s.w;
    #pragma unroll
    for (int o = 16; o; o >>= 1) ss += __shfl_xor_sync(0xFFFFFFFFu, ss, o);
    __shared__ float red[8];
    if ((t & 31) == 0) red[t >> 5] = ss;
    __syncthreads();
    if (t == 0) {
        float tot = 0.f;
        #pragma unroll
        for (int w = 0; w < 8; w++) tot += red[w];
        g_xnorm[b] = sqrtf(tot);
    }
}

// ---------------------------------------------------------------------------
// Kernel 3: fp16 mma GEMM (R11 config: TKH=64, A via cp.async, B via
// streaming LDG+cvt register pipeline, double-buffered, 3 CTAs/SM). Fused
// y-norms + out_sim + per-(batch,block) top-6. grid=NBLK, block=256.
// ---------------------------------------------------------------------------
__global__ void __launch_bounds__(256, 3) gemm_kernel(const float* __restrict__ lex,
                                                      float* __restrict__ out_sim) {
    extern __shared__ char smem8[];
    const uint32_t su = (uint32_t)__cvta_generic_to_shared(smem8);
    float* s_xn = reinterpret_cast<float*>(smem8 + OFS_XN);
    float* s_yn = reinterpret_cast<float*>(smem8 + OFS_YN);
    float* Cs   = reinterpret_cast<float*>(smem8);              // overlay
    u64*   tmp  = reinterpret_cast<u64*>(smem8 + OFS_TMP);      // overlay

    int tid = threadIdx.x;
    int v0 = blockIdx.x * TNB;
    int lane = tid & 31, wid = tid >> 5;
    int g = lane >> 2, t4 = lane & 3;
    int m_base = (wid >> 2) * 32;
    int n_base = (wid & 3) * 32;

    if (tid < BB) s_xn[tid] = g_xnorm[tid];

    // ldmatrix per-lane byte offsets (row stride = 144B; conflict-free)
    const int a_moff = (((lane >> 3) & 1) << 3) + (lane & 7);
    const int a_khi  = (lane >> 4) << 4;
    const uint32_t a_lane_off = (uint32_t)((m_base + a_moff) * 144 + a_khi);
    const int b_noff = ((lane >> 4) << 3) + (lane & 7);
    const int b_k8   = (((lane >> 3) & 1) << 4);
    const uint32_t b_lane_off = (uint32_t)(OFS_B + (n_base + b_noff) * 144 + b_k8);

    // B loader: 8 threads/row, rows brow+32i, two float4 per row (k-halves)
    const int brow = tid >> 3;
    const int bq   = (tid & 7) * 4;

    float acc[2][4][4];
    #pragma unroll
    for (int mt = 0; mt < 2; mt++)
        #pragma unroll
        for (int nt = 0; nt < 4; nt++)
            #pragma unroll
            for (int r = 0; r < 4; r++) acc[mt][nt][r] = 0.f;
    float yacc[4] = {0.f, 0.f, 0.f, 0.f};

    uint2 b_pre[8];

    #define ISSUE_A(buf, k0) do {                                              \
        _Pragma("unroll")                                                      \
        for (int j = 0; j < 2; j++) {                                          \
            int idx = tid + 256 * j;                                           \
            int row = idx >> 3, c = idx & 7;                                   \
            uint32_t dst = su + (buf) * A_STG + (uint32_t)(row * 144 + c * 16);\
            const __half* src = &g_ts16[row][(k0) + c * 8];                    \
            asm volatile("cp.async.cg.shared.global [%0], [%1], 16;"           \
                         :: "r"(dst), "l"(src) : "memory");                    \
        }                                                                      \
        asm volatile("cp.async.commit_group;" ::: "memory");                   \
    } while (0)

    #define LOAD_B(k0) do {                                                    \
        _Pragma("unroll")                                                      \
        for (int i = 0; i < 4; i++) {                                          \
            int v = v0 + brow + 32 * i;                                        \
            float4 w0 = make_float4(0.f, 0.f, 0.f, 0.f), w1 = w0;              \
            if (v < VV) {                                                      \
                const float* r = &lex[(size_t)v * DD + (k0)];                  \
                w0 = ldcs4(r + bq);                                            \
                w1 = ldcs4(r + 32 + bq);                                       \
            }                                                                  \
            yacc[i] += w0.x*w0.x + w0.y*w0.y + w0.z*w0.z + w0.w*w0.w           \
                     + w1.x*w1.x + w1.y*w1.y + w1.z*w1.z + w1.w*w1.w;          \
            b_pre[2*i].x   = h2u(__float22half2_rn(make_float2(w0.x, w0.y)));  \
            b_pre[2*i].y   = h2u(__float22half2_rn(make_float2(w0.z, w0.w)));  \
            b_pre[2*i+1].x = h2u(__float22half2_rn(make_float2(w1.x, w1.y)));  \
            b_pre[2*i+1].y = h2u(__float22half2_rn(make_float2(w1.z, w1.w)));  \
        }                                                                      \
    } while (0)

    #define STS_B(buf) do {                                                    \
        __half* Bb = reinterpret_cast<__half*>(smem8 + OFS_B + (buf) * B_STG); \
        _Pragma("unroll")                                                      \
        for (int i = 0; i < 4; i++) {                                          \
            *reinterpret_cast<uint2*>(&Bb[(brow + 32*i) * KPADH + bq])      = b_pre[2*i]; \
            *reinterpret_cast<uint2*>(&Bb[(brow + 32*i) * KPADH + 32 + bq]) = b_pre[2*i+1]; \
        }                                                                      \
    } while (0)

    // ---- prologue: tile 0 into buffer 0 ----
    ISSUE_A(0, 0);
    LOAD_B(0);
    STS_B(0);
    asm volatile("cp.async.wait_group 0;" ::: "memory");
    __syncthreads();

    for (int it = 0; it < NIT; it++) {
        int cur = it & 1;
        if (it < NIT - 1) {
            int k0 = (it + 1) * TKH;
            ISSUE_A(1 - cur, k0);
            LOAD_B(k0);
        }
        // ---- compute on current buffer ----
        {
            const uint32_t Acur = su + (uint32_t)(cur * A_STG);
            const uint32_t Bcur = su + (uint32_t)(cur * B_STG);  // b_lane_off has OFS_B
            #pragma unroll
            for (int ks = 0; ks < 4; ks++) {
                uint32_t a[2][4], bf[4][2];
                #pragma unroll
                for (int mt = 0; mt < 2; mt++)
                    ldsm4(a[mt][0], a[mt][1], a[mt][2], a[mt][3],
                          Acur + a_lane_off + (uint32_t)(mt * 16 * 144 + ks * 32));
                #pragma unroll
                for (int p = 0; p < 2; p++)
                    ldsm4(bf[2 * p][0], bf[2 * p][1], bf[2 * p + 1][0], bf[2 * p + 1][1],
                          Bcur + b_lane_off + (uint32_t)(p * 16 * 144 + ks * 32));
                #pragma unroll
                for (int mt = 0; mt < 2; mt++)
                    #pragma unroll
                    for (int nt = 0; nt < 4; nt++)
                        mma_f16(acc[mt][nt], a[mt][0], a[mt][1], a[mt][2], a[mt][3],
                                bf[nt][0], bf[nt][1]);
            }
        }
        if (it < NIT - 1) {
            STS_B(1 - cur);
            asm volatile("cp.async.wait_group 0;" ::: "memory");
            __syncthreads();
        }
    }

    // ---- y norms: reduce over the 8 threads sharing each row ----
    #pragma unroll
    for (int i = 0; i < 4; i++) {
        float ys = yacc[i];
        ys += __shfl_down_sync(0xFFFFFFFFu, ys, 4, 8);
        ys += __shfl_down_sync(0xFFFFFFFFu, ys, 2, 8);
        ys += __shfl_down_sync(0xFFFFFFFFu, ys, 1, 8);
        if ((tid & 7) == 0) {
            int n = brow + 32 * i;
            float yn = sqrtf(ys);
            s_yn[n] = yn;
            if (v0 + n < VV) g_ynorm[v0 + n] = yn;
        }
    }
    __syncthreads();  // tiles free; s_yn ready; overlay begins

    // ---- stage normalized tile in smem ----
    #pragma unroll
    for (int mt = 0; mt < 2; mt++) {
        int m0 = m_base + 16 * mt + g;
        float xn0 = s_xn[m0], xn1 = s_xn[m0 + 8];
        #pragma unroll
        for (int nt = 0; nt < 4; nt++) {
            int ncol = n_base + 8 * nt + 2 * t4;
            #pragma unroll
            for (int j = 0; j < 2; j++) {
                int v = v0 + ncol + j;
                float yn = s_yn[ncol + j];
                float s0 = acc[mt][nt][j]     / fmaxf(xn0 * yn, 1e-8f);
                float s1 = acc[mt][nt][2 + j] / fmaxf(xn1 * yn, 1e-8f);
                if (v >= VV) { s0 = -3.4e38f; s1 = -3.4e38f; }
                Cs[m0 * CSPAD + ncol + j]       = s0;
                Cs[(m0 + 8) * CSPAD + ncol + j] = s1;
            }
        }
    }
    __syncthreads();

    // ---- coalesced out_sim write ----
    #pragma unroll
    for (int i = 0; i < 32; i++) {
        int idx = tid + i * 256;
        int m = idx >> 7, col = idx & 127;
        int v = v0 + col;
        if (v < VV)
            out_sim[(size_t)m * VV + v] = Cs[m * CSPAD + col];
    }

    // ---- per-row top-6: 4 threads/row, 32 cols each ----
    {
        int row = tid >> 2, q = tid & 3;
        u64 t6[BTOP] = {0, 0, 0, 0, 0, 0};
        #pragma unroll
        for (int i = 0; i < 32; i++) {
            int col = q * 32 + i;
            int v = v0 + col;
            if (v < VV) insK<BTOP>(t6, mkkey(Cs[row * CSPAD + col], v));
        }
        #pragma unroll
        for (int i = 0; i < BTOP; i++) tmp[tid * BTOP + i] = t6[i];
    }
    __syncthreads();
    if (tid < BB) {
        u64 t6[BTOP] = {0, 0, 0, 0, 0, 0};
        #pragma unroll
        for (int q = 0; q < 4; q++)
            #pragma unroll
            for (int i = 0; i < BTOP; i++)
                insK<BTOP>(t6, tmp[(tid * 4 + q) * BTOP + i]);
        #pragma unroll
        for (int i = 0; i < BTOP; i++) g_btop[tid][blockIdx.x][i] = t6[i];
    }
}

// ---------------------------------------------------------------------------
// Kernel 4: merge. Phase A: top-5 over per-block MAXES (valid conservative
// threshold: at most 4 block maxes exceed the true 5th value). Phase B:
// skip-scan. Phase C: exact fp32 recompute. Phase D: exact select. Phase E:
// PARALLEL gather (all 5 rows in one latency exposure). grid=BB, block=512.
// ---------------------------------------------------------------------------
__global__ void __launch_bounds__(512) merge_kernel(const float* __restrict__ lex,
                                                    float* __restrict__ out_topk) {
    int b = blockIdx.x;
    int t = threadIdx.x;
    int lane = t & 31, wid = t >> 5;

    __shared__ u64   wtop[16][5];
    __shared__ float s_thresh;
    __shared__ int   cand[NCAND];
    __shared__ float cval[NCAND];
    __shared__ int   ncand;
    __shared__ int   selci[TOPK];
    __shared__ int   selfin[TOPK];

    const u64* keys = &g_btop[b][0][0];

    // Phase A: top-5 over block maxes (keys[blk*BTOP], sorted desc per block)
    u64 t5[5] = {0, 0, 0, 0, 0};
    if (t < NBLK) insK<5>(t5, keys[(size_t)t * BTOP]);
    #pragma unroll
    for (int o = 16; o; o >>= 1) {
        u64 ot[5];
        #pragma unroll
        for (int i = 0; i < 5; i++) ot[i] = __shfl_xor_sync(0xFFFFFFFFu, t5[i], o);
        #pragma unroll
        for (int i = 0; i < 5; i++) insK<5>(t5, ot[i]);
    }
    if (lane == 0) {
        #pragma unroll
        for (int i = 0; i < 5; i++) wtop[wid][i] = t5[i];
    }
    __syncthreads();
    if (wid == 0) {
        const u64* flat = &wtop[0][0];  // 80 keys
        u64 m5[5] = {0, 0, 0, 0, 0};
        insK<5>(m5, flat[lane]);
        insK<5>(m5, flat[lane + 32]);
        if (lane < 16) insK<5>(m5, flat[lane + 64]);
        #pragma unroll
        for (int o = 16; o; o >>= 1) {
            u64 ot[5];
            #pragma unroll
            for (int i = 0; i < 5; i++) ot[i] = __shfl_xor_sync(0xFFFFFFFFu, m5[i], o);
            #pragma unroll
            for (int i = 0; i < 5; i++) insK<5>(m5, ot[i]);
        }
        if (lane == 0) {
            s_thresh = funord((unsigned)(m5[4] >> 32)) - 5e-4f;
            ncand = 0;
        }
    }
    __syncthreads();

    // Phase B: skip-scan blocks whose max >= thresh
    float thr = s_thresh;
    if (t < NBLK) {
        u64 k0 = keys[(size_t)t * BTOP];
        if (funord((unsigned)(k0 >> 32)) >= thr) {
            #pragma unroll
            for (int j = 0; j < BTOP; j++) {
                u64 k = keys[(size_t)t * BTOP + j];
                if (funord((unsigned)(k >> 32)) >= thr) {
                    int slot = atomicAdd(&ncand, 1);
                    if (slot < NCAND) cand[slot] = key2idx(k);
                }
            }
        }
    }
    __syncthreads();
    int nc = min(ncand, NCAND);

    // Phase C: exact fp32 recompute (one warp per candidate, 16 warps)
    {
        const float4* ts4 = reinterpret_cast<const float4*>(g_tse[b]);
        for (int ci = wid; ci < nc; ci += 16) {
            int v = cand[ci];
            const float4* lx4 = reinterpret_cast<const float4*>(lex + (size_t)v * DD);
            float d = 0.f;
            #pragma unroll
            for (int j = 0; j < 8; j++) {
                float4 a = ts4[j * 32 + lane];
                float4 c = lx4[j * 32 + lane];
                d += a.x * c.x + a.y * c.y + a.z * c.z + a.w * c.w;
            }
            #pragma unroll
            for (int o = 16; o; o >>= 1) d += __shfl_xor_sync(0xFFFFFFFFu, d, o);
            if (lane == 0)
                cval[ci] = d / fmaxf(g_xnorm[b] * g_ynorm[v], 1e-8f);
        }
    }
    __syncthreads();

    // Phase D: exact top-5 over candidates (warp 0), tie-break lowest index
    if (t < 32) {
        for (int j = 0; j < TOPK; j++) {
            float bv = -1e30f;
            int bvi = 0x7FFFFFFF;
            int bci = -1;
            for (int ci = t; ci < nc; ci += 32) {
                bool used = false;
                #pragma unroll
                for (int jj = 0; jj < TOPK; jj++)
                    if (jj < j && selci[jj] == ci) used = true;
                if (used) continue;
                float x = cval[ci];
                int v = cand[ci];
                if (x > bv || (x == bv && v < bvi)) { bv = x; bvi = v; bci = ci; }
            }
            #pragma unroll
            for (int o = 16; o; o >>= 1) {
                float ov  = __shfl_xor_sync(0xFFFFFFFFu, bv, o);
                int   ovi = __shfl_xor_sync(0xFFFFFFFFu, bvi, o);
                int   oci = __shfl_xor_sync(0xFFFFFFFFu, bci, o);
                if (ov > bv || (ov == bv && ovi < bvi)) { bv = ov; bvi = ovi; bci = oci; }
            }
            if (t == 0) { selci[j] = bci; selfin[j] = bvi; }
            __syncwarp();
        }
    }
    __syncthreads();

    // Phase E: gather all TOPK rows in parallel (single latency exposure)
    for (int idx = t; idx < TOPK * (DD / 4); idx += 512) {
        int j = idx >> 8;              // row 0..4
        int d = idx & 255;             // float4 within row
        const float4* src = reinterpret_cast<const float4*>(lex + (size_t)selfin[j] * DD);
        float4* dst = reinterpret_cast<float4*>(out_topk + ((size_t)b * TOPK + j) * DD);
        dst[d] = src[d];
    }
}

// ---------------------------------------------------------------------------
extern "C" void kernel_launch(void* const* d_in, const int* in_sizes, int n_in,
                              void* d_out, int out_size) {
    const float* patch = (const float*)d_in[0];
    const float* lex   = (const float*)d_in[1];
    float* out      = (float*)d_out;
    float* out_topk = out;                                  // [64][5][1024]
    float* out_sim  = out + (size_t)BB * TOPK * DD;         // [64][50257]

    cudaFuncSetAttribute(gemm_kernel, cudaFuncAttributeMaxDynamicSharedMemorySize,
                         GEMM_SMEM);

    mean_partial_kernel<<<dim3(NCHUNK, BB), 256>>>(patch);
    finalize_kernel<<<BB, 256>>>();
    nop_kernel<<<1, 32>>>();   // shim: keeps gemm in the profiled launch slot
    gemm_kernel<<<NBLK, 256, GEMM_SMEM>>>(lex, out_sim);
    merge_kernel<<<BB, 512>>>(lex, out_topk);
}